// round 3
// baseline (speedup 1.0000x reference)
#include <cuda_runtime.h>

#define NN 50000
#define NE 640000
#define F  128
#define NC 16
#define BN_EPS 1e-5f

// ---------------- scratch (__device__ globals; no allocation allowed) ----------------
__device__ int   g_flag64;
__device__ int   g_cnt[NN];
__device__ int   g_cur[NN];
__device__ int   g_rowptr[NN + 1];
__device__ int   g_col[NE];
__device__ float g_dinv[NN];
__device__ float g_h[(size_t)NN * F];
__device__ float g_x[(size_t)NN * F];

// ---------------- edge dtype sniff: int64 vs int32 ----------------
// node ids are in [0, 50000) and non-negative; if stored as int64 (LE), every
// odd int32 word is 0. If int32, odd words are random node ids (P(all 64 == 0) ~ 0).
__global__ void sniff_k(const void* ei) {
    if (blockIdx.x == 0 && threadIdx.x == 0) {
        const int* p = (const int*)ei;
        int f = 1;
        for (int i = 0; i < 64; i++)
            if (p[2 * i + 1] != 0) { f = 0; break; }
        g_flag64 = f;
    }
}

__device__ __forceinline__ void load_edge(const void* ei, int e, int f64, int& s, int& d) {
    if (f64) {
        const long long* p = (const long long*)ei;
        s = (int)p[e];
        d = (int)p[NE + e];
    } else {
        const int* p = (const int*)ei;
        s = p[e];
        d = p[NE + e];
    }
}

// ---------------- CSR build ----------------
__global__ void zero_cnt_k() {
    int i = blockIdx.x * blockDim.x + threadIdx.x;
    if (i < NN) g_cnt[i] = 0;
}

__global__ void count_k(const void* ei) {
    int e = blockIdx.x * blockDim.x + threadIdx.x;
    int f64 = g_flag64;
    if (e < NE) {
        int s, d;
        load_edge(ei, e, f64, s, d);
        atomicAdd(&g_cnt[d], 1);
    }
}

__global__ void dinv_k() {
    int i = blockIdx.x * blockDim.x + threadIdx.x;
    if (i < NN) g_dinv[i] = rsqrtf((float)g_cnt[i] + 1.0f);  // +1 self loop
}

// single-block exclusive scan of g_cnt -> g_rowptr (and cursor copy)
__global__ void scan_k() {
    __shared__ int sh[1024];
    const int CH = (NN + 1023) / 1024;  // 49
    int t = threadIdx.x;
    int beg = t * CH;
    int end = beg + CH; if (end > NN) end = NN;
    int s = 0;
    for (int i = beg; i < end; i++) s += g_cnt[i];
    sh[t] = s;
    __syncthreads();
    for (int off = 1; off < 1024; off <<= 1) {
        int v = (t >= off) ? sh[t - off] : 0;
        __syncthreads();
        sh[t] += v;
        __syncthreads();
    }
    int run = (t == 0) ? 0 : sh[t - 1];
    for (int i = beg; i < end; i++) {
        g_rowptr[i] = run;
        g_cur[i] = run;
        run += g_cnt[i];
    }
    if (t == 0) g_rowptr[NN] = NE;
}

__global__ void fill_k(const void* ei) {
    int e = blockIdx.x * blockDim.x + threadIdx.x;
    int f64 = g_flag64;
    if (e < NE) {
        int s, d;
        load_edge(ei, e, f64, s, d);
        int pos = atomicAdd(&g_cur[d], 1);
        g_col[pos] = s;
    }
}

// ---------------- dense GEMM: Y[N,128] = X[N,128] @ W[128,128] ----------------
// 64-node x 128-col tile per block, 256 threads, W + X tile in dynamic smem.
#define GEMM_TM 64
#define XST 132  // padded row stride (floats); 132*4=528 bytes, multiple of 16

__global__ void gemm_k(const float* __restrict__ X, const float* __restrict__ W,
                       float* __restrict__ Y, int N) {
    extern __shared__ float sm[];
    float* Ws = sm;                 // [128*128]
    float* Xs = sm + F * F;         // [64 * XST]

    int tid = threadIdx.x;
    const float4* W4 = (const float4*)W;
    float4* Ws4 = (float4*)Ws;
    for (int i = tid; i < F * F / 4; i += 256) Ws4[i] = W4[i];

    int base = blockIdx.x * GEMM_TM;
    for (int i = tid; i < GEMM_TM * 32; i += 256) {
        int r = i >> 5, c4 = i & 31;
        int gr = base + r;
        float4 v = make_float4(0.f, 0.f, 0.f, 0.f);
        if (gr < N) v = ((const float4*)X)[(size_t)gr * 32 + c4];
        *(float4*)&Xs[r * XST + c4 * 4] = v;
    }
    __syncthreads();

    int colg = tid & 15;   // 0..15
    int rowg = tid >> 4;   // 0..15
    int c0 = colg * 4;     // cols [c0..c0+3] and [c0+64..c0+67] (conflict-free LDS.128)
    int r0 = rowg * 4;

    float acc[4][8];
#pragma unroll
    for (int i = 0; i < 4; i++)
#pragma unroll
        for (int j = 0; j < 8; j++) acc[i][j] = 0.f;

#pragma unroll 4
    for (int k = 0; k < F; k++) {
        float x0 = Xs[(r0 + 0) * XST + k];
        float x1 = Xs[(r0 + 1) * XST + k];
        float x2 = Xs[(r0 + 2) * XST + k];
        float x3 = Xs[(r0 + 3) * XST + k];
        float4 wA = *(const float4*)&Ws[k * F + c0];
        float4 wB = *(const float4*)&Ws[k * F + c0 + 64];
        acc[0][0] += x0 * wA.x; acc[0][1] += x0 * wA.y; acc[0][2] += x0 * wA.z; acc[0][3] += x0 * wA.w;
        acc[0][4] += x0 * wB.x; acc[0][5] += x0 * wB.y; acc[0][6] += x0 * wB.z; acc[0][7] += x0 * wB.w;
        acc[1][0] += x1 * wA.x; acc[1][1] += x1 * wA.y; acc[1][2] += x1 * wA.z; acc[1][3] += x1 * wA.w;
        acc[1][4] += x1 * wB.x; acc[1][5] += x1 * wB.y; acc[1][6] += x1 * wB.z; acc[1][7] += x1 * wB.w;
        acc[2][0] += x2 * wA.x; acc[2][1] += x2 * wA.y; acc[2][2] += x2 * wA.z; acc[2][3] += x2 * wA.w;
        acc[2][4] += x2 * wB.x; acc[2][5] += x2 * wB.y; acc[2][6] += x2 * wB.z; acc[2][7] += x2 * wB.w;
        acc[3][0] += x3 * wA.x; acc[3][1] += x3 * wA.y; acc[3][2] += x3 * wA.z; acc[3][3] += x3 * wA.w;
        acc[3][4] += x3 * wB.x; acc[3][5] += x3 * wB.y; acc[3][6] += x3 * wB.z; acc[3][7] += x3 * wB.w;
    }

#pragma unroll
    for (int i = 0; i < 4; i++) {
        int gr = base + r0 + i;
        if (gr < N) {
            float4 a = make_float4(acc[i][0], acc[i][1], acc[i][2], acc[i][3]);
            float4 b = make_float4(acc[i][4], acc[i][5], acc[i][6], acc[i][7]);
            ((float4*)Y)[(size_t)gr * 32 + colg] = a;
            ((float4*)Y)[(size_t)gr * 32 + 16 + colg] = b;
        }
    }
}

// ---------------- aggregation: warp per node, float4 per lane ----------------
// MODE 0: out = agg + bias
// MODE 1: out = relu((agg + bias - mean) * rsqrt(var+eps) * gamma + beta)
template <int MODE>
__global__ void agg_k(const float* __restrict__ h, float* __restrict__ out,
                      const float* __restrict__ bias, const float* __restrict__ gamma,
                      const float* __restrict__ beta, const float* __restrict__ mean,
                      const float* __restrict__ var) {
    int gw = (blockIdx.x * blockDim.x + threadIdx.x) >> 5;
    int lane = threadIdx.x & 31;
    if (gw >= NN) return;
    int n = gw;
    float dn = g_dinv[n];
    const float4* h4 = (const float4*)h;

    float4 acc = h4[(size_t)n * 32 + lane];  // self loop
    float w0 = dn * dn;
    acc.x *= w0; acc.y *= w0; acc.z *= w0; acc.w *= w0;

    int jb = g_rowptr[n], je = g_rowptr[n + 1];
    for (int j = jb; j < je; j++) {
        int s = g_col[j];
        float w = g_dinv[s] * dn;
        float4 v = h4[(size_t)s * 32 + lane];
        acc.x += v.x * w; acc.y += v.y * w; acc.z += v.z * w; acc.w += v.w * w;
    }

    float4 b = ((const float4*)bias)[lane];
    float4 o;
    if (MODE == 1) {
        float4 gm = ((const float4*)gamma)[lane];
        float4 bt = ((const float4*)beta)[lane];
        float4 mn = ((const float4*)mean)[lane];
        float4 vr = ((const float4*)var)[lane];
        o.x = fmaxf(0.f, (acc.x + b.x - mn.x) * rsqrtf(vr.x + BN_EPS) * gm.x + bt.x);
        o.y = fmaxf(0.f, (acc.y + b.y - mn.y) * rsqrtf(vr.y + BN_EPS) * gm.y + bt.y);
        o.z = fmaxf(0.f, (acc.z + b.z - mn.z) * rsqrtf(vr.z + BN_EPS) * gm.z + bt.z);
        o.w = fmaxf(0.f, (acc.w + b.w - mn.w) * rsqrtf(vr.w + BN_EPS) * gm.w + bt.w);
    } else {
        o.x = acc.x + b.x; o.y = acc.y + b.y; o.z = acc.z + b.z; o.w = acc.w + b.w;
    }
    ((float4*)out)[(size_t)n * 32 + lane] = o;
}

// ---------------- classifier: out[N,16] = X[N,128] @ Wc[128,16] + bc ----------------
__global__ void cls_k(const float* __restrict__ X, const float* __restrict__ Wc,
                      const float* __restrict__ bc, float* __restrict__ Y) {
    __shared__ float Ws[F * NC];
    __shared__ float bs[NC];
    int tid = threadIdx.x;
    for (int i = tid; i < F * NC; i += 256) Ws[i] = Wc[i];
    if (tid < NC) bs[tid] = bc[tid];
    __syncthreads();

    int idx = blockIdx.x * 256 + tid;
    if (idx >= NN * NC) return;
    int n = idx >> 4, c = idx & 15;
    float acc = bs[c];
    const float4* xr = (const float4*)(X + (size_t)n * F);
#pragma unroll
    for (int k4 = 0; k4 < 32; k4++) {
        float4 v = xr[k4];
        int kb = k4 * 4;
        acc += v.x * Ws[(kb + 0) * NC + c] + v.y * Ws[(kb + 1) * NC + c] +
               v.z * Ws[(kb + 2) * NC + c] + v.w * Ws[(kb + 3) * NC + c];
    }
    Y[idx] = acc;
}

// ---------------- launch ----------------
extern "C" void kernel_launch(void* const* d_in, const int* in_sizes, int n_in,
                              void* d_out, int out_size) {
    const float* seq   = (const float*)d_in[0];
    const void*  ei    = d_in[1];
    const float* W1    = (const float*)d_in[2];
    const float* b1    = (const float*)d_in[3];
    const float* gamma = (const float*)d_in[4];
    const float* beta  = (const float*)d_in[5];
    const float* rmean = (const float*)d_in[6];
    const float* rvar  = (const float*)d_in[7];
    const float* W2    = (const float*)d_in[8];
    const float* b2    = (const float*)d_in[9];
    const float* Wc    = (const float*)d_in[10];
    const float* bc    = (const float*)d_in[11];
    float* out = (float*)d_out;

    float* gh = nullptr;
    float* gx = nullptr;
    cudaGetSymbolAddress((void**)&gh, g_h);
    cudaGetSymbolAddress((void**)&gx, g_x);

    int smem = (F * F + GEMM_TM * XST) * (int)sizeof(float);  // 99328 bytes
    cudaFuncSetAttribute(gemm_k, cudaFuncAttributeMaxDynamicSharedMemorySize, smem);

    // CSR build (shared by both conv layers)
    sniff_k<<<1, 32>>>(ei);
    zero_cnt_k<<<(NN + 255) / 256, 256>>>();
    count_k<<<NE / 256, 256>>>(ei);
    dinv_k<<<(NN + 255) / 256, 256>>>();
    scan_k<<<1, 1024>>>();
    fill_k<<<NE / 256, 256>>>(ei);

    int gemm_blocks = (NN + GEMM_TM - 1) / GEMM_TM;
    int agg_blocks = (NN * 32 + 255) / 256;

    // layer 1: h = seq @ W1 ; agg + b1 -> BN -> ReLU
    gemm_k<<<gemm_blocks, 256, smem>>>(seq, W1, gh, NN);
    agg_k<1><<<agg_blocks, 256>>>(gh, gx, b1, gamma, beta, rmean, rvar);

    // layer 2: h = x @ W2 ; agg + b2
    gemm_k<<<gemm_blocks, 256, smem>>>(gx, W2, gh, NN);
    agg_k<0><<<agg_blocks, 256>>>(gh, gx, b2, nullptr, nullptr, nullptr, nullptr);

    // classifier
    cls_k<<<(NN * NC + 255) / 256, 256>>>(gx, Wc, bc, out);
}

// round 4
// speedup vs baseline: 1.2714x; 1.2714x over previous
#include <cuda_runtime.h>

#define NN 50000
#define NE 640000
#define F  128
#define NC 16
#define BN_EPS 1e-5f

// ---------------- scratch (__device__ globals; no allocation allowed) ----------------
__device__ int   g_flag64;
__device__ int   g_cnt[NN];
__device__ int   g_cur[NN];
__device__ int   g_rowptr[NN + 1];
__device__ int   g_col[NE];
__device__ float g_dinv[NN];
__device__ float g_h[(size_t)NN * F];
__device__ float g_x[(size_t)NN * F];
__device__ float g_t[(size_t)NN * NC];   // x @ Wf  (N x 16)
__device__ float g_wf[F * NC];           // W2 @ Wc (128 x 16)
__device__ float g_bf[NC];               // b2 @ Wc + bc

// ---------------- edge dtype sniff: int64 vs int32 ----------------
// node ids are in [0, 50000) and non-negative; if stored as int64 (LE), every
// odd int32 word is 0. If int32, odd words are random node ids (P(all 64 == 0) ~ 0).
__global__ void sniff_k(const void* ei) {
    if (blockIdx.x == 0 && threadIdx.x == 0) {
        const int* p = (const int*)ei;
        int f = 1;
        for (int i = 0; i < 64; i++)
            if (p[2 * i + 1] != 0) { f = 0; break; }
        g_flag64 = f;
    }
}

__device__ __forceinline__ void load_edge(const void* ei, int e, int f64, int& s, int& d) {
    if (f64) {
        const long long* p = (const long long*)ei;
        s = (int)p[e];
        d = (int)p[NE + e];
    } else {
        const int* p = (const int*)ei;
        s = p[e];
        d = p[NE + e];
    }
}

// ---------------- CSR build ----------------
__global__ void zero_cnt_k() {
    int i = blockIdx.x * blockDim.x + threadIdx.x;
    if (i < NN) g_cnt[i] = 0;
}

__global__ void count_k(const void* ei) {
    int e = blockIdx.x * blockDim.x + threadIdx.x;
    int f64 = g_flag64;
    if (e < NE) {
        int s, d;
        load_edge(ei, e, f64, s, d);
        atomicAdd(&g_cnt[d], 1);
    }
}

__global__ void dinv_k() {
    int i = blockIdx.x * blockDim.x + threadIdx.x;
    if (i < NN) g_dinv[i] = rsqrtf((float)g_cnt[i] + 1.0f);  // +1 self loop
}

// single-block exclusive scan of g_cnt -> g_rowptr (and cursor copy)
__global__ void scan_k() {
    __shared__ int sh[1024];
    const int CH = (NN + 1023) / 1024;  // 49
    int t = threadIdx.x;
    int beg = t * CH;
    int end = beg + CH; if (end > NN) end = NN;
    int s = 0;
    for (int i = beg; i < end; i++) s += g_cnt[i];
    sh[t] = s;
    __syncthreads();
    for (int off = 1; off < 1024; off <<= 1) {
        int v = (t >= off) ? sh[t - off] : 0;
        __syncthreads();
        sh[t] += v;
        __syncthreads();
    }
    int run = (t == 0) ? 0 : sh[t - 1];
    for (int i = beg; i < end; i++) {
        g_rowptr[i] = run;
        g_cur[i] = run;
        run += g_cnt[i];
    }
    if (t == 0) g_rowptr[NN] = NE;
}

__global__ void fill_k(const void* ei) {
    int e = blockIdx.x * blockDim.x + threadIdx.x;
    int f64 = g_flag64;
    if (e < NE) {
        int s, d;
        load_edge(ei, e, f64, s, d);
        int pos = atomicAdd(&g_cur[d], 1);
        g_col[pos] = s;
    }
}

// ---------------- fused weight precompute: Wf = W2 @ Wc, bf = b2 @ Wc + bc ----
// grid 8 x 256 = 2048 threads, one per (i, c) of the 128x16 output.
__global__ void fusew_k(const float* __restrict__ W2, const float* __restrict__ Wc,
                        const float* __restrict__ b2, const float* __restrict__ bc) {
    __shared__ float Wcs[F * NC];
    int tid = threadIdx.x;
    for (int i = tid; i < F * NC; i += 256) Wcs[i] = Wc[i];
    __syncthreads();

    int g = blockIdx.x * 256 + tid;   // 0..2047
    int i = g >> 4, c = g & 15;
    float acc = 0.f;
    const float* w2r = W2 + (size_t)i * F;
#pragma unroll 8
    for (int k = 0; k < F; k++) acc += w2r[k] * Wcs[k * NC + c];
    g_wf[i * NC + c] = acc;

    if (g < NC) {
        float a = bc[g];
        for (int k = 0; k < F; k++) a += b2[k] * Wcs[k * NC + g];
        g_bf[g] = a;
    }
}

// ---------------- dense GEMM: Y[N,128] = X[N,128] @ W[128,128] ----------------
#define GEMM_TM 64
#define XST 132  // padded row stride (floats)

__global__ void gemm_k(const float* __restrict__ X, const float* __restrict__ W,
                       float* __restrict__ Y, int N) {
    extern __shared__ float sm[];
    float* Ws = sm;                 // [128*128]
    float* Xs = sm + F * F;         // [64 * XST]

    int tid = threadIdx.x;
    const float4* W4 = (const float4*)W;
    float4* Ws4 = (float4*)Ws;
    for (int i = tid; i < F * F / 4; i += 256) Ws4[i] = W4[i];

    int base = blockIdx.x * GEMM_TM;
    for (int i = tid; i < GEMM_TM * 32; i += 256) {
        int r = i >> 5, c4 = i & 31;
        int gr = base + r;
        float4 v = make_float4(0.f, 0.f, 0.f, 0.f);
        if (gr < N) v = ((const float4*)X)[(size_t)gr * 32 + c4];
        *(float4*)&Xs[r * XST + c4 * 4] = v;
    }
    __syncthreads();

    int colg = tid & 15;
    int rowg = tid >> 4;
    int c0 = colg * 4;
    int r0 = rowg * 4;

    float acc[4][8];
#pragma unroll
    for (int i = 0; i < 4; i++)
#pragma unroll
        for (int j = 0; j < 8; j++) acc[i][j] = 0.f;

#pragma unroll 4
    for (int k = 0; k < F; k++) {
        float x0 = Xs[(r0 + 0) * XST + k];
        float x1 = Xs[(r0 + 1) * XST + k];
        float x2 = Xs[(r0 + 2) * XST + k];
        float x3 = Xs[(r0 + 3) * XST + k];
        float4 wA = *(const float4*)&Ws[k * F + c0];
        float4 wB = *(const float4*)&Ws[k * F + c0 + 64];
        acc[0][0] += x0 * wA.x; acc[0][1] += x0 * wA.y; acc[0][2] += x0 * wA.z; acc[0][3] += x0 * wA.w;
        acc[0][4] += x0 * wB.x; acc[0][5] += x0 * wB.y; acc[0][6] += x0 * wB.z; acc[0][7] += x0 * wB.w;
        acc[1][0] += x1 * wA.x; acc[1][1] += x1 * wA.y; acc[1][2] += x1 * wA.z; acc[1][3] += x1 * wA.w;
        acc[1][4] += x1 * wB.x; acc[1][5] += x1 * wB.y; acc[1][6] += x1 * wB.z; acc[1][7] += x1 * wB.w;
        acc[2][0] += x2 * wA.x; acc[2][1] += x2 * wA.y; acc[2][2] += x2 * wA.z; acc[2][3] += x2 * wA.w;
        acc[2][4] += x2 * wB.x; acc[2][5] += x2 * wB.y; acc[2][6] += x2 * wB.z; acc[2][7] += x2 * wB.w;
        acc[3][0] += x3 * wA.x; acc[3][1] += x3 * wA.y; acc[3][2] += x3 * wA.z; acc[3][3] += x3 * wA.w;
        acc[3][4] += x3 * wB.x; acc[3][5] += x3 * wB.y; acc[3][6] += x3 * wB.z; acc[3][7] += x3 * wB.w;
    }

#pragma unroll
    for (int i = 0; i < 4; i++) {
        int gr = base + r0 + i;
        if (gr < N) {
            float4 a = make_float4(acc[i][0], acc[i][1], acc[i][2], acc[i][3]);
            float4 b = make_float4(acc[i][4], acc[i][5], acc[i][6], acc[i][7]);
            ((float4*)Y)[(size_t)gr * 32 + colg] = a;
            ((float4*)Y)[(size_t)gr * 32 + 16 + colg] = b;
        }
    }
}

// ---------------- narrow GEMM: T[N,16] = X[N,128] @ g_wf[128,16] (no bias) ----
__global__ void gemm16_k(const float* __restrict__ X, float* __restrict__ T) {
    __shared__ float Ws[F * NC];
    int tid = threadIdx.x;
    for (int i = tid; i < F * NC; i += 256) Ws[i] = g_wf[i];
    __syncthreads();

    int idx = blockIdx.x * 256 + tid;
    if (idx >= NN * NC) return;
    int n = idx >> 4, c = idx & 15;
    float acc = 0.f;
    const float4* xr = (const float4*)(X + (size_t)n * F);
#pragma unroll
    for (int k4 = 0; k4 < 32; k4++) {
        float4 v = xr[k4];
        int kb = k4 * 4;
        acc += v.x * Ws[(kb + 0) * NC + c] + v.y * Ws[(kb + 1) * NC + c] +
               v.z * Ws[(kb + 2) * NC + c] + v.w * Ws[(kb + 3) * NC + c];
    }
    T[idx] = acc;
}

// ---------------- aggregation (128 feats): warp per node, float4 per lane -----
// out = relu((agg + bias - mean) * rsqrt(var+eps) * gamma + beta)
__global__ void agg128_bn_k(const float* __restrict__ h, float* __restrict__ out,
                            const float* __restrict__ bias, const float* __restrict__ gamma,
                            const float* __restrict__ beta, const float* __restrict__ mean,
                            const float* __restrict__ var) {
    int gw = (blockIdx.x * blockDim.x + threadIdx.x) >> 5;
    int lane = threadIdx.x & 31;
    if (gw >= NN) return;
    int n = gw;
    float dn = g_dinv[n];
    const float4* h4 = (const float4*)h;

    float4 acc = h4[(size_t)n * 32 + lane];  // self loop
    float w0 = dn * dn;
    acc.x *= w0; acc.y *= w0; acc.z *= w0; acc.w *= w0;

    int jb = g_rowptr[n], je = g_rowptr[n + 1];
    for (int j = jb; j < je; j++) {
        int s = g_col[j];
        float w = g_dinv[s] * dn;
        float4 v = h4[(size_t)s * 32 + lane];
        acc.x += v.x * w; acc.y += v.y * w; acc.z += v.z * w; acc.w += v.w * w;
    }

    float4 b = ((const float4*)bias)[lane];
    float4 gm = ((const float4*)gamma)[lane];
    float4 bt = ((const float4*)beta)[lane];
    float4 mn = ((const float4*)mean)[lane];
    float4 vr = ((const float4*)var)[lane];
    float4 o;
    o.x = fmaxf(0.f, (acc.x + b.x - mn.x) * rsqrtf(vr.x + BN_EPS) * gm.x + bt.x);
    o.y = fmaxf(0.f, (acc.y + b.y - mn.y) * rsqrtf(vr.y + BN_EPS) * gm.y + bt.y);
    o.z = fmaxf(0.f, (acc.z + b.z - mn.z) * rsqrtf(vr.z + BN_EPS) * gm.z + bt.z);
    o.w = fmaxf(0.f, (acc.w + b.w - mn.w) * rsqrtf(vr.w + BN_EPS) * gm.w + bt.w);
    ((float4*)out)[(size_t)n * 32 + lane] = o;
}

// ---------------- aggregation (16 feats): 4 threads per node, float4 each -----
// out = agg(t) + g_bf   (writes final output)
__global__ void agg16_k(const float* __restrict__ t, float* __restrict__ out) {
    int idx = blockIdx.x * blockDim.x + threadIdx.x;
    int n = idx >> 2;
    int q = idx & 3;
    if (n >= NN) return;
    float dn = g_dinv[n];
    const float4* t4 = (const float4*)t;

    float4 acc = t4[(size_t)n * 4 + q];  // self loop
    float w0 = dn * dn;
    acc.x *= w0; acc.y *= w0; acc.z *= w0; acc.w *= w0;

    int jb = g_rowptr[n], je = g_rowptr[n + 1];
    for (int j = jb; j < je; j++) {
        int s = g_col[j];
        float w = g_dinv[s] * dn;
        float4 v = t4[(size_t)s * 4 + q];
        acc.x += v.x * w; acc.y += v.y * w; acc.z += v.z * w; acc.w += v.w * w;
    }

    float4 b = ((const float4*)g_bf)[q];
    acc.x += b.x; acc.y += b.y; acc.z += b.z; acc.w += b.w;
    ((float4*)out)[(size_t)n * 4 + q] = acc;
}

// ---------------- launch ----------------
extern "C" void kernel_launch(void* const* d_in, const int* in_sizes, int n_in,
                              void* d_out, int out_size) {
    const float* seq   = (const float*)d_in[0];
    const void*  ei    = d_in[1];
    const float* W1    = (const float*)d_in[2];
    const float* b1    = (const float*)d_in[3];
    const float* gamma = (const float*)d_in[4];
    const float* beta  = (const float*)d_in[5];
    const float* rmean = (const float*)d_in[6];
    const float* rvar  = (const float*)d_in[7];
    const float* W2    = (const float*)d_in[8];
    const float* b2    = (const float*)d_in[9];
    const float* Wc    = (const float*)d_in[10];
    const float* bc    = (const float*)d_in[11];
    float* out = (float*)d_out;

    float* gh = nullptr;
    float* gx = nullptr;
    float* gt = nullptr;
    cudaGetSymbolAddress((void**)&gh, g_h);
    cudaGetSymbolAddress((void**)&gx, g_x);
    cudaGetSymbolAddress((void**)&gt, g_t);

    int smem = (F * F + GEMM_TM * XST) * (int)sizeof(float);  // 99328 bytes
    cudaFuncSetAttribute(gemm_k, cudaFuncAttributeMaxDynamicSharedMemorySize, smem);

    // CSR build (shared by both conv layers) + fused classifier weights
    sniff_k<<<1, 32>>>(ei);
    zero_cnt_k<<<(NN + 255) / 256, 256>>>();
    count_k<<<NE / 256, 256>>>(ei);
    dinv_k<<<(NN + 255) / 256, 256>>>();
    scan_k<<<1, 1024>>>();
    fill_k<<<NE / 256, 256>>>(ei);
    fusew_k<<<8, 256>>>(W2, Wc, b2, bc);

    int gemm_blocks = (NN + GEMM_TM - 1) / GEMM_TM;

    // layer 1: h = seq @ W1 ; agg + b1 -> BN -> ReLU
    gemm_k<<<gemm_blocks, 256, smem>>>(seq, W1, gh, NN);
    agg128_bn_k<<<(NN * 32 + 255) / 256, 256>>>(gh, gx, b1, gamma, beta, rmean, rvar);

    // layer 2 + classifier fused: out = agg(x @ (W2@Wc)) + (b2@Wc + bc)
    gemm16_k<<<(NN * NC + 255) / 256, 256>>>(gx, gt);
    agg16_k<<<(NN * 4 + 255) / 256, 256>>>(gt, out);
}